// round 16
// baseline (speedup 1.0000x reference)
#include <cuda_runtime.h>
#include <cuda_fp16.h>
#include <math.h>
#include <stdint.h>

#define BB 4
#define NN 4096
#define DD 1024
#define HH 16
#define HDIM 64
#define GG 512
#define BNTOK (BB*NN)

// ---------------- scratch (device globals; no allocations allowed) ----------
__device__ float  g_field[(size_t)BB * HH * GG * HDIM]; // 8MB
__device__ float  g_mag [(size_t)BNTOK * HH];           // 1MB  ||k|| per (token, head)
__device__ float  g_S   [(size_t)BB * GG * HH];         // 128KB sum of mags per (bin, head)
__device__ __half g_kw  [(size_t)DD * DD];              // 2MB
__device__ __half g_vw  [(size_t)DD * DD];              // 2MB
__device__ __half g_ow  [(size_t)DD * DD];              // 2MB
__device__ __half g_Y   [(size_t)HH * BB * GG * DD];    // 64MB segsum, layout [h][bin][d]
__device__ __half g_A   [(size_t)BB * GG * DD];         // 4MB  conv result, repacked

// Replicates jnp: pos = (n/4095.0f)*511.0f ; int32 trunc ; clip
__device__ __forceinline__ int bin_of(int n) {
    float p = ((float)n / 4095.0f) * 511.0f;
    int g = (int)p;
    g = g < 0 ? 0 : g;
    return g > 511 ? 511 : g;
}

// ---------------- baseline-PTX tensor helpers (sm_80+, ok on compute_103) ---
__device__ __forceinline__ uint32_t smem_u32(const void* p) {
    uint32_t a;
    asm("{ .reg .u64 t; cvta.to.shared.u64 t, %1; cvt.u32.u64 %0, t; }" : "=r"(a) : "l"(p));
    return a;
}
__device__ __forceinline__ void ldmx4(uint32_t* r, uint32_t a) {
    asm volatile("ldmatrix.sync.aligned.m8n8.x4.shared.b16 {%0,%1,%2,%3}, [%4];"
        : "=r"(r[0]), "=r"(r[1]), "=r"(r[2]), "=r"(r[3]) : "r"(a));
}
__device__ __forceinline__ void mma16816(float* c, const uint32_t* a, const uint32_t* b) {
    asm volatile("mma.sync.aligned.m16n8k16.row.col.f32.f16.f16.f32 "
        "{%0,%1,%2,%3}, {%4,%5,%6,%7}, {%8,%9}, {%0,%1,%2,%3};"
        : "+f"(c[0]), "+f"(c[1]), "+f"(c[2]), "+f"(c[3])
        : "r"(a[0]), "r"(a[1]), "r"(a[2]), "r"(a[3]), "r"(b[0]), "r"(b[1]));
}
#define CP_ASYNC(d, s) asm volatile("cp.async.cg.shared.global [%0], [%1], 16;" :: "r"(d), "l"(s) : "memory")
#define CP_COMMIT()    asm volatile("cp.async.commit_group;" ::: "memory")
#define CP_WAIT2()     asm volatile("cp.async.wait_group 2;" ::: "memory")
#define CP_WAIT1()     asm volatile("cp.async.wait_group 1;" ::: "memory")
#define CP_WAIT0()     asm volatile("cp.async.wait_group 0;" ::: "memory")

#define KC    64
#define NCH   16                  // 1024 / 64

// swizzled byte offset for (row, 16B-chunk c in 0..7)
__device__ __forceinline__ uint32_t swz(uint32_t row, uint32_t c) {
    return row * 128u + ((c ^ (row & 7u)) << 4);
}

// generic tile loader (cp.async both operands): BOFF = AROWS*128.
template <int NTHR, int AROWS, int BROWS, int BOFF>
__device__ __forceinline__ void load_tiles(
    const __half* __restrict__ gA, size_t strideA,
    const __half* __restrict__ gB, size_t strideB,
    uint32_t sbase, int t)
{
    #pragma unroll
    for (int i = 0; i < AROWS * 8 / NTHR; ++i) {
        int e = t + i * NTHR;
        int row = e >> 3, c = e & 7;
        CP_ASYNC(sbase + swz(row, c), gA + (size_t)row * strideA + c * 8);
    }
    #pragma unroll
    for (int i = 0; i < BROWS * 8 / NTHR; ++i) {
        int e = t + i * NTHR;
        int row = e >> 3, c = e & 7;
        CP_ASYNC(sbase + BOFF + swz(row, c), gB + (size_t)row * strideB + c * 8);
    }
}

// 64x32 warp-tile compute over one KC=64 stage, separate A/B smem bases
__device__ __forceinline__ void compute64x32_AB(uint32_t Ab, uint32_t Bb,
                                                int m0w, int n0w, int lane,
                                                float acc[4][4][4])
{
    #pragma unroll
    for (int kh = 0; kh < 4; ++kh) {
        uint32_t ah[4][4];
        uint32_t arow = (uint32_t)(m0w + (lane & 15));
        uint32_t ac   = (uint32_t)(kh * 2 + (lane >> 4));
        #pragma unroll
        for (int mt = 0; mt < 4; ++mt)
            ldmx4(ah[mt], Ab + swz(arow + mt * 16, ac));
        uint32_t bh[2][4];
        uint32_t brow = (uint32_t)(n0w + (lane & 7) + ((lane >> 4) << 3));
        uint32_t bc   = (uint32_t)(kh * 2 + ((lane & 8) >> 3));
        #pragma unroll
        for (int bj = 0; bj < 2; ++bj)
            ldmx4(bh[bj], Bb + swz(brow + bj * 16, bc));
        #pragma unroll
        for (int mt = 0; mt < 4; ++mt)
            #pragma unroll
            for (int nt = 0; nt < 4; ++nt)
                mma16816(acc[mt][nt], ah[mt], &bh[nt >> 1][(nt & 1) * 2]);
    }
}

// 32x32 warp-tile compute over one KC=64 stage (A tile 64 rows; BOFF 8192)
__device__ __forceinline__ void compute32x32(uint32_t st, int m0w, int n0w, int lane,
                                             float acc[2][4][4])
{
    #pragma unroll
    for (int kh = 0; kh < 4; ++kh) {
        uint32_t ah[2][4];
        uint32_t arow = (uint32_t)(m0w + (lane & 15));
        uint32_t ac   = (uint32_t)(kh * 2 + (lane >> 4));
        #pragma unroll
        for (int mt = 0; mt < 2; ++mt)
            ldmx4(ah[mt], st + swz(arow + mt * 16, ac));
        uint32_t bh[2][4];
        uint32_t brow = (uint32_t)(n0w + (lane & 7) + ((lane >> 4) << 3));
        uint32_t bc   = (uint32_t)(kh * 2 + ((lane & 8) >> 3));
        #pragma unroll
        for (int bj = 0; bj < 2; ++bj)
            ldmx4(bh[bj], st + 8192 + swz(brow + bj * 16, bc));
        #pragma unroll
        for (int mt = 0; mt < 2; ++mt)
            #pragma unroll
            for (int nt = 0; nt < 4; ++nt)
                mma16816(acc[mt][nt], ah[mt], &bh[nt >> 1][(nt & 1) * 2]);
    }
}

// ---------------------------------------------------------------------------
// prep: weights only (kw, vw, ow) fp32 -> fp16
// ---------------------------------------------------------------------------
__global__ void prep_kernel(const float* __restrict__ kw, const float* __restrict__ vw,
                            const float* __restrict__ ow)
{
    int bid = blockIdx.x;
    const float* src; __half2* dst; size_t i;
    if (bid < 1024)       { src = kw; dst = (__half2*)g_kw; i = (size_t)bid * 256 + threadIdx.x; }
    else if (bid < 2048)  { src = vw; dst = (__half2*)g_vw; i = (size_t)(bid - 1024) * 256 + threadIdx.x; }
    else                  { src = ow; dst = (__half2*)g_ow; i = (size_t)(bid - 2048) * 256 + threadIdx.x; }
    float4 v = reinterpret_cast<const float4*>(src)[i];
    dst[2*i]   = __half2(__float2half(v.x), __float2half(v.y));
    dst[2*i+1] = __half2(__float2half(v.z), __float2half(v.w));
}

// ---------------------------------------------------------------------------
// GEMM #1 (k only): K = x @ kw^T with INLINE fp32->fp16 A conversion.
// Block 128 tokens x 128 cols (2 heads), 8 warps, 64x32 tiles.
// A: LDG fp32 -> cvt -> STS, double-buffered. B: cp.async, triple-buffered.
// Two __syncthreads per K-step (wait->sync->storeA->compute->sync). 2 CTAs/SM.
// smem: A0 0 | A1 16K | B0 32K | B1 48K | B2 64K  = 80KB
// ---------------------------------------------------------------------------
#define KSMEM 81920
__global__ __launch_bounds__(256, 2) void k_gemm_kernel(
    const float* __restrict__ x, const float* __restrict__ kb)
{
    extern __shared__ char sp[];
    __shared__ float s_kb[128];
    __shared__ float s_part[128][4];
    const int t    = threadIdx.x;
    const int lane = t & 31;
    const int w    = t >> 5;
    const int m0w  = (w >> 2) * 64;
    const int n0w  = (w & 3) * 32;
    const int m0   = blockIdx.x * 128;
    const int pair = blockIdx.y;          // heads 2*pair, 2*pair+1
    const int n0   = pair * 128;
    uint32_t sb = smem_u32(sp);
    const uint32_t A0 = sb, A1 = sb + 16384, Bb = sb + 32768;

    if (t < 128) s_kb[t] = kb[pair * 128 + t];

    float acc[4][4][4];
    #pragma unroll
    for (int a = 0; a < 4; ++a)
        #pragma unroll
        for (int b = 0; b < 4; ++b)
            #pragma unroll
            for (int q = 0; q < 4; ++q) acc[a][b][q] = 0.f;

    const float*  Xbase = x    + (size_t)m0 * DD;
    const __half* Wbase = g_kw + (size_t)n0 * DD;

    // prologue: A(0) synchronous LDG + cvt + STS into A0
    #pragma unroll
    for (int i = 0; i < 4; ++i) {
        int e = t + i * 256;
        int row = e >> 3, c = e & 7;
        const float4* src = reinterpret_cast<const float4*>(Xbase + (size_t)row * DD + c * 8);
        float4 v0 = src[0], v1 = src[1];
        __half2 p0 = __floats2half2_rn(v0.x, v0.y), p1 = __floats2half2_rn(v0.z, v0.w);
        __half2 p2 = __floats2half2_rn(v1.x, v1.y), p3 = __floats2half2_rn(v1.z, v1.w);
        uint4 u;
        u.x = *reinterpret_cast<uint32_t*>(&p0); u.y = *reinterpret_cast<uint32_t*>(&p1);
        u.z = *reinterpret_cast<uint32_t*>(&p2); u.w = *reinterpret_cast<uint32_t*>(&p3);
        *reinterpret_cast<uint4*>(sp + swz(row, c)) = u;
    }
    // B(0), B(1) via cp.async
    #pragma unroll
    for (int kc = 0; kc < 2; ++kc) {
        #pragma unroll
        for (int i = 0; i < 4; ++i) {
            int e = t + i * 256;
            int row = e >> 3, c = e & 7;
            CP_ASYNC(Bb + kc * 16384 + swz(row, c),
                     Wbase + (size_t)row * DD + kc * KC + c * 8);
        }
        CP_COMMIT();
    }
    __syncthreads();   // A(0) visible

    for (int s = 0; s < NCH; ++s) {
        float4 hold[8];
        const bool haveNext = (s + 1 < NCH);
        if (haveNext) {
            #pragma unroll
            for (int i = 0; i < 4; ++i) {
                int e = t + i * 256;
                int row = e >> 3, c = e & 7;
                const float4* src = reinterpret_cast<const float4*>(
                    Xbase + (size_t)row * DD + (s + 1) * KC + c * 8);
                hold[2*i]     = src[0];
                hold[2*i + 1] = src[1];
            }
        }
        if (s + 2 < NCH) {
            #pragma unroll
            for (int i = 0; i < 4; ++i) {
                int e = t + i * 256;
                int row = e >> 3, c = e & 7;
                CP_ASYNC(Bb + ((s + 2) % 3) * 16384 + swz(row, c),
                         Wbase + (size_t)row * DD + (s + 2) * KC + c * 8);
            }
            CP_COMMIT();
            CP_WAIT2();
        } else if (haveNext) { CP_WAIT1(); } else { CP_WAIT0(); }
        __syncthreads();   // B(s) visible to ALL threads (cp.async needs barrier after wait)

        if (haveNext) {
            // store A(s+1) into the opposite buffer (last read in compute(s-1),
            // all threads exited it at the previous barrier) — frees hold regs.
            char* dstA = sp + (((s + 1) & 1) ? 16384 : 0);
            #pragma unroll
            for (int i = 0; i < 4; ++i) {
                int e = t + i * 256;
                int row = e >> 3, c = e & 7;
                float4 v0 = hold[2*i], v1 = hold[2*i + 1];
                __half2 p0 = __floats2half2_rn(v0.x, v0.y), p1 = __floats2half2_rn(v0.z, v0.w);
                __half2 p2 = __floats2half2_rn(v1.x, v1.y), p3 = __floats2half2_rn(v1.z, v1.w);
                uint4 u;
                u.x = *reinterpret_cast<uint32_t*>(&p0); u.y = *reinterpret_cast<uint32_t*>(&p1);
                u.z = *reinterpret_cast<uint32_t*>(&p2); u.w = *reinterpret_cast<uint32_t*>(&p3);
                *reinterpret_cast<uint4*>(dstA + swz(row, c)) = u;
            }
        }

        compute64x32_AB((s & 1) ? A1 : A0, Bb + (s % 3) * 16384, m0w, n0w, lane, acc);
        __syncthreads();   // A(s+1) visible; compute(s) done before buffer reuse
    }

    // epilogue: per-row ssq partial over this warp's 32 cols, butterfly, combine
    #pragma unroll
    for (int mt = 0; mt < 4; ++mt)
        #pragma unroll
        for (int half = 0; half < 2; ++half) {
            float ssq = 0.f;
            #pragma unroll
            for (int nt = 0; nt < 4; ++nt) {
                int cl = n0w + nt * 8 + ((lane & 3) << 1);
                float k0 = acc[mt][nt][half * 2 + 0] + s_kb[cl];
                float k1 = acc[mt][nt][half * 2 + 1] + s_kb[cl + 1];
                ssq = fmaf(k0, k0, fmaf(k1, k1, ssq));
            }
            ssq += __shfl_xor_sync(0xFFFFFFFF, ssq, 1);
            ssq += __shfl_xor_sync(0xFFFFFFFF, ssq, 2);
            if ((lane & 3) == 0)
                s_part[m0w + mt * 16 + half * 8 + (lane >> 2)][w & 3] = ssq;
        }
    __syncthreads();

    if (t < 128) {
        int tok = m0 + t;
        g_mag[(size_t)tok * HH + pair * 2]     = sqrtf(s_part[t][0] + s_part[t][1]);
        g_mag[(size_t)tok * HH + pair * 2 + 1] = sqrtf(s_part[t][2] + s_part[t][3]);
    }
}

// ---------------------------------------------------------------------------
// ysum: Y[h][bin][:] = sum_{n in bin} mag[n,h] * x[n,:]; S[bin,h] = sum mag
// Reads fp32 x directly. One block per bin, 512 threads (float2 per thread).
// ---------------------------------------------------------------------------
__global__ void ysum_kernel(const float* __restrict__ x)
{
    __shared__ float sm[9 * 16];
    const int m = blockIdx.x;            // b*512 + g
    const int b = m >> 9, g = m & 511;
    const int t = threadIdx.x;

    int n = (int)(((long long)g * 4095) / 511) - 2;
    if (n < 0) n = 0;
    while (bin_of(n) < g) ++n;
    const int ns = n;
    int ne = n;
    while (ne < NN && bin_of(ne) == g) ++ne;
    const int cnt = ne - ns;             // 1..9

    if (t < cnt * 16)
        sm[t] = g_mag[((size_t)(b * NN + ns + (t >> 4))) * HH + (t & 15)];
    __syncthreads();

    __half2* Y2 = reinterpret_cast<__half2*>(g_Y);
    float2 xf[9];
    for (int i = 0; i < cnt; ++i)
        xf[i] = *reinterpret_cast<const float2*>(
            x + ((size_t)(b * NN + ns + i)) * DD + 2 * t);
    for (int h = 0; h < 16; ++h) {
        float2 s = make_float2(0.f, 0.f);
        for (int i = 0; i < cnt; ++i) {
            float wgt = sm[i * 16 + h];
            s.x = fmaf(wgt, xf[i].x, s.x);
            s.y = fmaf(wgt, xf[i].y, s.y);
        }
        Y2[(((size_t)h * (BB * GG) + m) << 9) + t] = __floats2half2_rn(s.x, s.y);
    }
    if (t < 16) {
        float s = 0.f;
        for (int i = 0; i < cnt; ++i) s += sm[i * 16 + t];
        g_S[(size_t)m * HH + t] = s;
    }
}

// ---------------------------------------------------------------------------
// GEMM #2: field[bin,h,:] = Y[h][bin][:] @ vw_h^T + S*vb_h
// Block 64 bins x 64 cols, 4 warps (32x32 tiles), 3-stage x16KB, 4 CTAs/SM.
// Y rows contiguous (stride DD).
// ---------------------------------------------------------------------------
#define FSTAGE 16384
__global__ __launch_bounds__(128, 4) void f_gemm_kernel(const float* __restrict__ vb)
{
    extern __shared__ char sp[];
    __shared__ float s_vb[64], s_S[64];
    const int t    = threadIdx.x;
    const int lane = t & 31;
    const int w    = t >> 5;
    const int m0w  = (w >> 1) * 32;
    const int n0w  = (w & 1) * 32;
    const int m0   = blockIdx.x * 64;     // bins (b*512+g)
    const int h    = blockIdx.y;
    uint32_t sb = smem_u32(sp);

    if (t < 64)       s_vb[t]      = vb[h * 64 + t];
    else if (t < 128) s_S[t - 64]  = g_S[(size_t)(m0 + t - 64) * HH + h];

    float acc[2][4][4];
    #pragma unroll
    for (int a = 0; a < 2; ++a)
        #pragma unroll
        for (int b = 0; b < 4; ++b)
            #pragma unroll
            for (int q = 0; q < 4; ++q) acc[a][b][q] = 0.f;

    const __half* Abase = g_Y  + ((size_t)h * (BB * GG) + m0) * DD;
    const __half* Bbase = g_vw + (size_t)(h * 64) * DD;

    load_tiles<128,64,64,8192>(Abase,      DD, Bbase,      DD, sb,          t); CP_COMMIT();
    load_tiles<128,64,64,8192>(Abase + KC, DD, Bbase + KC, DD, sb + FSTAGE, t); CP_COMMIT();

    for (int s = 0; s < NCH; ++s) {
        if (s + 2 < NCH) { CP_WAIT1(); } else { CP_WAIT0(); }
        __syncthreads();
        if (s + 2 < NCH) {
            load_tiles<128,64,64,8192>(Abase + (s + 2) * KC, DD, Bbase + (s + 2) * KC, DD,
                                       sb + ((s + 2) % 3) * FSTAGE, t);
            CP_COMMIT();
        }
        compute32x32(sb + (s % 3) * FSTAGE, m0w, n0w, lane, acc);
    }

    #pragma unroll
    for (int mt = 0; mt < 2; ++mt)
        #pragma unroll
        for (int half = 0; half < 2; ++half) {
            int mloc = m0w + mt * 16 + half * 8 + (lane >> 2);
            int m = m0 + mloc;
            int b = m >> 9, g = m & 511;
            float Sv = s_S[mloc];
            float* dst = g_field + ((((size_t)(b * HH + h)) * GG + g) << 6);
            #pragma unroll
            for (int nt = 0; nt < 4; ++nt) {
                int cl = n0w + nt * 8 + ((lane & 3) << 1);
                float2 o;
                o.x = acc[mt][nt][half * 2 + 0] + Sv * s_vb[cl];
                o.y = acc[mt][nt][half * 2 + 1] + Sv * s_vb[cl + 1];
                *reinterpret_cast<float2*>(dst + cl) = o;
            }
        }
}

// ---------------------------------------------------------------------------
// circular exp-kernel convolution; writes out-GEMM A matrix (fp16) directly
// ---------------------------------------------------------------------------
#define TAPS 144
__global__ void conv_kernel()
{
    extern __shared__ float sf[];
    __shared__ float wsh[TAPS];
    int bh = blockIdx.x;
    int b  = bh >> 4, h = bh & 15;
    const float* F = g_field + (size_t)bh * GG * HDIM;
    for (int i = threadIdx.x; i < GG * HDIM; i += blockDim.x)
        sf[i] = F[i];
    if (threadIdx.x < TAPS) {
        float Z = 0.f;
        for (int dd = 256; dd >= 1; --dd) Z += expf(-(float)dd / 3.0f);
        Z += 1e-8f;
        wsh[threadIdx.x] = expf(-(float)(threadIdx.x + 1) / 3.0f) / Z;
    }
    __syncthreads();

    int d    = threadIdx.x & 63;
    int g0   = (threadIdx.x >> 6) * 64;
    int gtop = g0 + 63;

    float acc = 0.f;
    for (int j = TAPS - 1; j >= 0; --j)
        acc = fmaf(wsh[j], sf[((gtop + 257 + j) & 511) * HDIM + d], acc);

    __half* outA = g_A + ((size_t)b * GG << 10) + h * 64 + d;
    outA[(size_t)gtop << 10] = __float2half(acc);

    const float a  = 0.7165313105737893f;
    const float w0 = wsh[0];
    float C = acc;
    for (int g = gtop - 1; g >= g0; --g) {
        C = fmaf(a, C, w0 * sf[((g + 257) & 511) * HDIM + d]);
        outA[(size_t)g << 10] = __float2half(C);
    }
}

// ---------------------------------------------------------------------------
// GEMM #3: out rows = A @ ow^T + ob, scattered to all tokens per bin.
// Block 64 bins x 64 cols, 4 warps (32x32), 3-stage x16KB, 4 CTAs/SM.
// ---------------------------------------------------------------------------
__global__ __launch_bounds__(128, 4) void out_gemm_kernel(
    const float* __restrict__ ob, float* __restrict__ out)
{
    extern __shared__ char sp[];
    __shared__ float s_ob[64];
    const int t    = threadIdx.x;
    const int lane = t & 31;
    const int w    = t >> 5;
    const int m0w  = (w >> 1) * 32;
    const int n0w  = (w & 1) * 32;
    const int m0   = blockIdx.x * 64;     // rows m = b*512 + g
    const int j0   = blockIdx.y * 64;
    uint32_t sb = smem_u32(sp);

    if (t < 64) s_ob[t] = ob[j0 + t];

    float acc[2][4][4];
    #pragma unroll
    for (int a = 0; a < 2; ++a)
        #pragma unroll
        for (int b = 0; b < 4; ++b)
            #pragma unroll
            for (int q = 0; q < 4; ++q) acc[a][b][q] = 0.f;

    const __half* Abase = g_A  + (size_t)m0 * DD;
    const __half* Bbase = g_ow + (size_t)j0 * DD;

    load_tiles<128,64,64,8192>(Abase,      DD, Bbase,      DD, sb,          t); CP_COMMIT();
    load_tiles<128,64,64,8192>(Abase + KC, DD, Bbase + KC, DD, sb + FSTAGE, t); CP_COMMIT();

    for (int s = 0; s < NCH; ++s) {
        if (s + 2 < NCH) { CP_WAIT1(); } else { CP_WAIT0(); }
        __syncthreads();
        if (s + 2 < NCH) {
            load_tiles<128,64,64,8192>(Abase + (s + 2) * KC, DD, Bbase + (s + 2) * KC, DD,
                                       sb + ((s + 2) % 3) * FSTAGE, t);
            CP_COMMIT();
        }
        compute32x32(sb + (s % 3) * FSTAGE, m0w, n0w, lane, acc);
    }

    // scatter each bin-row to every token n with bin_of(n) == g
    const int b = m0 >> 9;
    #pragma unroll
    for (int mt = 0; mt < 2; ++mt) {
        #pragma unroll
        for (int half = 0; half < 2; ++half) {
            int m = m0 + m0w + mt * 16 + (lane >> 2) + half * 8;
            int g = m & 511;
            int n = (int)(((long long)g * 4095) / 511) - 2;
            if (n < 0) n = 0;
            while (bin_of(n) < g) ++n;
            for (; n < NN && bin_of(n) == g; ++n) {
                float* dst = out + (((size_t)(b * NN + n)) << 10) + j0;
                #pragma unroll
                for (int nt = 0; nt < 4; ++nt) {
                    int cl = n0w + nt * 8 + ((lane & 3) << 1);
                    float2 o;
                    o.x = acc[mt][nt][half * 2 + 0] + s_ob[cl];
                    o.y = acc[mt][nt][half * 2 + 1] + s_ob[cl + 1];
                    *reinterpret_cast<float2*>(dst + cl) = o;
                }
            }
        }
    }
}

// ---------------------------------------------------------------------------
extern "C" void kernel_launch(void* const* d_in, const int* in_sizes, int n_in,
                              void* d_out, int out_size)
{
    const float* x  = (const float*)d_in[0];
    // d_in[1], d_in[2] are q_w, q_b — unused by the reference output.
    const float* kw = (const float*)d_in[3];
    const float* kb = (const float*)d_in[4];
    const float* vw = (const float*)d_in[5];
    const float* vb = (const float*)d_in[6];
    const float* ow = (const float*)d_in[7];
    const float* ob = (const float*)d_in[8];
    float* out = (float*)d_out;

    cudaFuncSetAttribute(k_gemm_kernel,   cudaFuncAttributeMaxDynamicSharedMemorySize, KSMEM);
    cudaFuncSetAttribute(f_gemm_kernel,   cudaFuncAttributeMaxDynamicSharedMemorySize, 3 * FSTAGE);
    cudaFuncSetAttribute(out_gemm_kernel, cudaFuncAttributeMaxDynamicSharedMemorySize, 3 * FSTAGE);
    cudaFuncSetAttribute(conv_kernel, cudaFuncAttributeMaxDynamicSharedMemorySize,
                         GG * HDIM * (int)sizeof(float));

    prep_kernel<<<3072, 256>>>(kw, vw, ow);

    k_gemm_kernel<<<dim3(BNTOK / 128, 8), 256, KSMEM>>>(x, kb);

    ysum_kernel<<<BB * GG, 512>>>(x);

    f_gemm_kernel<<<dim3((BB * GG) / 64, HH), 128, 3 * FSTAGE>>>(vb);

    conv_kernel<<<BB * HH, 512, GG * HDIM * sizeof(float)>>>();

    out_gemm_kernel<<<dim3((BB * GG) / 64, DD / 64), 128, 3 * FSTAGE>>>(ob, out);
}

// round 17
// speedup vs baseline: 1.0915x; 1.0915x over previous
#include <cuda_runtime.h>
#include <cuda_fp16.h>
#include <math.h>
#include <stdint.h>

#define BB 4
#define NN 4096
#define DD 1024
#define HH 16
#define HDIM 64
#define GG 512
#define BNTOK (BB*NN)

// ---------------- scratch (device globals; no allocations allowed) ----------
__device__ float  g_field[(size_t)BB * HH * GG * HDIM]; // 8MB
__device__ float  g_mag [(size_t)BNTOK * HH];           // 1MB  ||k|| per (token, head)
__device__ float  g_S   [(size_t)BB * GG * HH];         // 128KB sum of mags per (bin, head)
__device__ __half g_x   [(size_t)BNTOK * DD];           // 32MB fp16 x
__device__ __half g_kw  [(size_t)DD * DD];              // 2MB
__device__ __half g_vw  [(size_t)DD * DD];              // 2MB
__device__ __half g_ow  [(size_t)DD * DD];              // 2MB
__device__ __half g_Y   [(size_t)BB * GG * HH * DD];    // 64MB weighted segsum of x
__device__ __half g_A   [(size_t)BB * GG * DD];         // 4MB  conv result, repacked

// Replicates jnp: pos = (n/4095.0f)*511.0f ; int32 trunc ; clip
__device__ __forceinline__ int bin_of(int n) {
    float p = ((float)n / 4095.0f) * 511.0f;
    int g = (int)p;
    g = g < 0 ? 0 : g;
    return g > 511 ? 511 : g;
}

// ---------------- baseline-PTX tensor helpers (sm_80+, ok on compute_103) ---
__device__ __forceinline__ uint32_t smem_u32(const void* p) {
    uint32_t a;
    asm("{ .reg .u64 t; cvta.to.shared.u64 t, %1; cvt.u32.u64 %0, t; }" : "=r"(a) : "l"(p));
    return a;
}
__device__ __forceinline__ void ldmx4(uint32_t* r, uint32_t a) {
    asm volatile("ldmatrix.sync.aligned.m8n8.x4.shared.b16 {%0,%1,%2,%3}, [%4];"
        : "=r"(r[0]), "=r"(r[1]), "=r"(r[2]), "=r"(r[3]) : "r"(a));
}
__device__ __forceinline__ void mma16816(float* c, const uint32_t* a, const uint32_t* b) {
    asm volatile("mma.sync.aligned.m16n8k16.row.col.f32.f16.f16.f32 "
        "{%0,%1,%2,%3}, {%4,%5,%6,%7}, {%8,%9}, {%0,%1,%2,%3};"
        : "+f"(c[0]), "+f"(c[1]), "+f"(c[2]), "+f"(c[3])
        : "r"(a[0]), "r"(a[1]), "r"(a[2]), "r"(a[3]), "r"(b[0]), "r"(b[1]));
}
#define CP_ASYNC(d, s) asm volatile("cp.async.cg.shared.global [%0], [%1], 16;" :: "r"(d), "l"(s) : "memory")
#define CP_COMMIT()    asm volatile("cp.async.commit_group;" ::: "memory")
#define CP_WAIT1()     asm volatile("cp.async.wait_group 1;" ::: "memory")
#define CP_WAIT0()     asm volatile("cp.async.wait_group 0;" ::: "memory")

#define KC    64
#define NCH   16                  // 1024 / 64

// swizzled byte offset for (row, 16B-chunk c in 0..7)
__device__ __forceinline__ uint32_t swz(uint32_t row, uint32_t c) {
    return row * 128u + ((c ^ (row & 7u)) << 4);
}

// generic tile loader: gA/gB pre-offset to (row0, kc*KC). BOFF = AROWS*128.
template <int NTHR, int AROWS, int BROWS, int BOFF>
__device__ __forceinline__ void load_tiles(
    const __half* __restrict__ gA, size_t strideA,
    const __half* __restrict__ gB, size_t strideB,
    uint32_t sbase, int t)
{
    #pragma unroll
    for (int i = 0; i < AROWS * 8 / NTHR; ++i) {
        int e = t + i * NTHR;
        int row = e >> 3, c = e & 7;
        CP_ASYNC(sbase + swz(row, c), gA + (size_t)row * strideA + c * 8);
    }
    #pragma unroll
    for (int i = 0; i < BROWS * 8 / NTHR; ++i) {
        int e = t + i * NTHR;
        int row = e >> 3, c = e & 7;
        CP_ASYNC(sbase + BOFF + swz(row, c), gB + (size_t)row * strideB + c * 8);
    }
}

// 32x64 warp-tile compute over one KC=64 stage (A tile 64 rows; BOFF 8192)
__device__ __forceinline__ void compute32x64(uint32_t st, int m0w, int n0w, int lane,
                                             float acc[2][8][4])
{
    #pragma unroll
    for (int kh = 0; kh < 4; ++kh) {
        uint32_t ah[2][4];
        uint32_t arow = (uint32_t)(m0w + (lane & 15));
        uint32_t ac   = (uint32_t)(kh * 2 + (lane >> 4));
        #pragma unroll
        for (int mt = 0; mt < 2; ++mt)
            ldmx4(ah[mt], st + swz(arow + mt * 16, ac));
        uint32_t bh[4][4];
        uint32_t brow = (uint32_t)(n0w + (lane & 7) + ((lane >> 4) << 3));
        uint32_t bc   = (uint32_t)(kh * 2 + ((lane & 8) >> 3));
        #pragma unroll
        for (int bj = 0; bj < 4; ++bj)
            ldmx4(bh[bj], st + 8192 + swz(brow + bj * 16, bc));
        #pragma unroll
        for (int mt = 0; mt < 2; ++mt)
            #pragma unroll
            for (int nt = 0; nt < 8; ++nt)
                mma16816(acc[mt][nt], ah[mt], &bh[nt >> 1][(nt & 1) * 2]);
    }
}

// 32x32 warp-tile compute over one KC=64 stage (A tile 64 rows; BOFF 8192)
__device__ __forceinline__ void compute32x32(uint32_t st, int m0w, int n0w, int lane,
                                             float acc[2][4][4])
{
    #pragma unroll
    for (int kh = 0; kh < 4; ++kh) {
        uint32_t ah[2][4];
        uint32_t arow = (uint32_t)(m0w + (lane & 15));
        uint32_t ac   = (uint32_t)(kh * 2 + (lane >> 4));
        #pragma unroll
        for (int mt = 0; mt < 2; ++mt)
            ldmx4(ah[mt], st + swz(arow + mt * 16, ac));
        uint32_t bh[2][4];
        uint32_t brow = (uint32_t)(n0w + (lane & 7) + ((lane >> 4) << 3));
        uint32_t bc   = (uint32_t)(kh * 2 + ((lane & 8) >> 3));
        #pragma unroll
        for (int bj = 0; bj < 2; ++bj)
            ldmx4(bh[bj], st + 8192 + swz(brow + bj * 16, bc));
        #pragma unroll
        for (int mt = 0; mt < 2; ++mt)
            #pragma unroll
            for (int nt = 0; nt < 4; ++nt)
                mma16816(acc[mt][nt], ah[mt], &bh[nt >> 1][(nt & 1) * 2]);
    }
}

// ---------------------------------------------------------------------------
// prep: all fp32->fp16 conversions merged in one launch
// ---------------------------------------------------------------------------
__global__ void prep_kernel(const float* __restrict__ x,  const float* __restrict__ kw,
                            const float* __restrict__ vw, const float* __restrict__ ow)
{
    int bid = blockIdx.x;
    const float* src; __half2* dst; size_t i;
    if (bid < 16384)      { src = x;  dst = (__half2*)g_x;  i = (size_t)bid * 256 + threadIdx.x; }
    else if (bid < 17408) { src = kw; dst = (__half2*)g_kw; i = (size_t)(bid - 16384) * 256 + threadIdx.x; }
    else if (bid < 18432) { src = vw; dst = (__half2*)g_vw; i = (size_t)(bid - 17408) * 256 + threadIdx.x; }
    else                  { src = ow; dst = (__half2*)g_ow; i = (size_t)(bid - 18432) * 256 + threadIdx.x; }
    float4 v = reinterpret_cast<const float4*>(src)[i];
    dst[2*i]   = __half2(__float2half(v.x), __float2half(v.y));
    dst[2*i+1] = __half2(__float2half(v.z), __float2half(v.w));
}

// ---------------------------------------------------------------------------
// GEMM #1 (k only): K = x @ kw^T, fused ||k+kb|| -> g_mag.
// Block 64 tokens x 128 cols (2 heads). 4 warps (2x2), warp tile 32x64,
// 2-stage x24KB = 48KB -> 4 CTAs/SM. Warp-local ||k|| reduction.
// ---------------------------------------------------------------------------
#define KSTAGE 24576
__global__ __launch_bounds__(128, 4) void k_gemm_kernel(const float* __restrict__ kb)
{
    extern __shared__ char sp[];
    __shared__ float s_kb[128];
    const int t    = threadIdx.x;
    const int lane = t & 31;
    const int w    = t >> 5;              // 0..3
    const int m0w  = (w >> 1) * 32;
    const int n0w  = (w & 1) * 64;
    const int m0   = blockIdx.x * 64;
    const int pair = blockIdx.y;          // heads 2*pair, 2*pair+1
    const int n0   = pair * 128;
    uint32_t sb = smem_u32(sp);

    if (t < 128) s_kb[t] = kb[pair * 128 + t];

    float acc[2][8][4];
    #pragma unroll
    for (int a = 0; a < 2; ++a)
        #pragma unroll
        for (int b = 0; b < 8; ++b)
            #pragma unroll
            for (int q = 0; q < 4; ++q) acc[a][b][q] = 0.f;

    const __half* Abase = g_x  + (size_t)m0 * DD;
    const __half* Bbase = g_kw + (size_t)n0 * DD;

    load_tiles<128,64,128,8192>(Abase, DD, Bbase, DD, sb, t); CP_COMMIT();

    for (int s = 0; s < NCH; ++s) {
        if (s + 1 < NCH) {
            load_tiles<128,64,128,8192>(Abase + (s + 1) * KC, DD, Bbase + (s + 1) * KC, DD,
                                        sb + ((s + 1) & 1) * KSTAGE, t);
            CP_COMMIT(); CP_WAIT1();
        } else { CP_WAIT0(); }
        __syncthreads();
        compute32x64(sb + (s & 1) * KSTAGE, m0w, n0w, lane, acc);
        __syncthreads();
    }

    // epilogue: warp-local ||k|| per row (this warp's 64 cols = one full head)
    const int head = pair * 2 + (n0w >> 6);
    #pragma unroll
    for (int mt = 0; mt < 2; ++mt)
        #pragma unroll
        for (int half = 0; half < 2; ++half) {
            float ssq = 0.f;
            #pragma unroll
            for (int nt = 0; nt < 8; ++nt) {
                int cl = n0w + nt * 8 + ((lane & 3) << 1);
                float k0 = acc[mt][nt][half * 2 + 0] + s_kb[cl];
                float k1 = acc[mt][nt][half * 2 + 1] + s_kb[cl + 1];
                ssq = fmaf(k0, k0, fmaf(k1, k1, ssq));
            }
            ssq += __shfl_xor_sync(0xFFFFFFFF, ssq, 1);
            ssq += __shfl_xor_sync(0xFFFFFFFF, ssq, 2);
            if ((lane & 3) == 0) {
                int tok = m0 + m0w + mt * 16 + half * 8 + (lane >> 2);
                g_mag[(size_t)tok * HH + head] = sqrtf(ssq);
            }
        }
}

// ---------------------------------------------------------------------------
// ysum: Y[bin,h,:] = sum_{n in bin} mag[n,h] * x[n,:]; S[bin,h] = sum mag
// One block per bin, 512 threads, half2-vectorized.
// ---------------------------------------------------------------------------
__global__ void ysum_kernel()
{
    __shared__ float sm[9 * 16];
    const int m = blockIdx.x;            // b*512 + g
    const int b = m >> 9, g = m & 511;
    const int t = threadIdx.x;

    int n = (int)(((long long)g * 4095) / 511) - 2;
    if (n < 0) n = 0;
    while (bin_of(n) < g) ++n;
    const int ns = n;
    int ne = n;
    while (ne < NN && bin_of(ne) == g) ++ne;
    const int cnt = ne - ns;             // 1..9

    if (t < cnt * 16)
        sm[t] = g_mag[((size_t)(b * NN + ns + (t >> 4))) * HH + (t & 15)];
    __syncthreads();

    const __half2* X2 = reinterpret_cast<const __half2*>(g_x);
    __half2* Y2 = reinterpret_cast<__half2*>(g_Y);
    float2 xf[9];
    for (int i = 0; i < cnt; ++i)
        xf[i] = __half22float2(X2[(((size_t)(b * NN + ns + i)) << 9) + t]);
    for (int h = 0; h < 16; ++h) {
        float2 s = make_float2(0.f, 0.f);
        for (int i = 0; i < cnt; ++i) {
            float wgt = sm[i * 16 + h];
            s.x = fmaf(wgt, xf[i].x, s.x);
            s.y = fmaf(wgt, xf[i].y, s.y);
        }
        Y2[(((size_t)m * HH + h) << 9) + t] = __floats2half2_rn(s.x, s.y);
    }
    if (t < 16) {
        float s = 0.f;
        for (int i = 0; i < cnt; ++i) s += sm[i * 16 + t];
        g_S[(size_t)m * HH + t] = s;
    }
}

// ---------------------------------------------------------------------------
// GEMM #2: field[bin,h,:] = Y[bin,h,:] @ vw_h^T + S*vb_h
// Block 64 bins x 64 cols, 4 warps (32x32 tiles), 3-stage x16KB, 4 CTAs/SM.
// ---------------------------------------------------------------------------
#define FSTAGE 16384
__global__ __launch_bounds__(128, 4) void f_gemm_kernel(const float* __restrict__ vb)
{
    extern __shared__ char sp[];
    __shared__ float s_vb[64], s_S[64];
    const int t    = threadIdx.x;
    const int lane = t & 31;
    const int w    = t >> 5;
    const int m0w  = (w >> 1) * 32;
    const int n0w  = (w & 1) * 32;
    const int m0   = blockIdx.x * 64;     // bins (b*512+g)
    const int h    = blockIdx.y;
    uint32_t sb = smem_u32(sp);

    if (t < 64)       s_vb[t]      = vb[h * 64 + t];
    else if (t < 128) s_S[t - 64]  = g_S[(size_t)(m0 + t - 64) * HH + h];

    float acc[2][4][4];
    #pragma unroll
    for (int a = 0; a < 2; ++a)
        #pragma unroll
        for (int b = 0; b < 4; ++b)
            #pragma unroll
            for (int q = 0; q < 4; ++q) acc[a][b][q] = 0.f;

    const __half* Abase = g_Y  + ((size_t)m0 * HH + h) * DD;
    const __half* Bbase = g_vw + (size_t)(h * 64) * DD;
    const size_t strA = (size_t)HH * DD;  // 16384

    load_tiles<128,64,64,8192>(Abase,      strA, Bbase,      DD, sb,          t); CP_COMMIT();
    load_tiles<128,64,64,8192>(Abase + KC, strA, Bbase + KC, DD, sb + FSTAGE, t); CP_COMMIT();

    for (int s = 0; s < NCH; ++s) {
        if (s + 2 < NCH) { CP_WAIT1(); } else { CP_WAIT0(); }
        __syncthreads();
        if (s + 2 < NCH) {
            load_tiles<128,64,64,8192>(Abase + (s + 2) * KC, strA, Bbase + (s + 2) * KC, DD,
                                       sb + ((s + 2) % 3) * FSTAGE, t);
            CP_COMMIT();
        }
        compute32x32(sb + (s % 3) * FSTAGE, m0w, n0w, lane, acc);
    }

    #pragma unroll
    for (int mt = 0; mt < 2; ++mt)
        #pragma unroll
        for (int half = 0; half < 2; ++half) {
            int mloc = m0w + mt * 16 + half * 8 + (lane >> 2);
            int m = m0 + mloc;
            int b = m >> 9, g = m & 511;
            float Sv = s_S[mloc];
            float* dst = g_field + ((((size_t)(b * HH + h)) * GG + g) << 6);
            #pragma unroll
            for (int nt = 0; nt < 4; ++nt) {
                int cl = n0w + nt * 8 + ((lane & 3) << 1);
                float2 o;
                o.x = acc[mt][nt][half * 2 + 0] + Sv * s_vb[cl];
                o.y = acc[mt][nt][half * 2 + 1] + Sv * s_vb[cl + 1];
                *reinterpret_cast<float2*>(dst + cl) = o;
            }
        }
}

// ---------------------------------------------------------------------------
// circular exp-kernel convolution; writes out-GEMM A matrix (fp16) directly
// ---------------------------------------------------------------------------
#define TAPS 144
__global__ void conv_kernel()
{
    extern __shared__ float sf[];
    __shared__ float wsh[TAPS];
    int bh = blockIdx.x;
    int b  = bh >> 4, h = bh & 15;
    const float* F = g_field + (size_t)bh * GG * HDIM;
    for (int i = threadIdx.x; i < GG * HDIM; i += blockDim.x)
        sf[i] = F[i];
    if (threadIdx.x < TAPS) {
        float Z = 0.f;
        for (int dd = 256; dd >= 1; --dd) Z += expf(-(float)dd / 3.0f);
        Z += 1e-8f;
        wsh[threadIdx.x] = expf(-(float)(threadIdx.x + 1) / 3.0f) / Z;
    }
    __syncthreads();

    int d    = threadIdx.x & 63;
    int g0   = (threadIdx.x >> 6) * 64;
    int gtop = g0 + 63;

    float acc = 0.f;
    for (int j = TAPS - 1; j >= 0; --j)
        acc = fmaf(wsh[j], sf[((gtop + 257 + j) & 511) * HDIM + d], acc);

    __half* outA = g_A + ((size_t)b * GG << 10) + h * 64 + d;
    outA[(size_t)gtop << 10] = __float2half(acc);

    const float a  = 0.7165313105737893f;
    const float w0 = wsh[0];
    float C = acc;
    for (int g = gtop - 1; g >= g0; --g) {
        C = fmaf(a, C, w0 * sf[((g + 257) & 511) * HDIM + d]);
        outA[(size_t)g << 10] = __float2half(C);
    }
}

// ---------------------------------------------------------------------------
// GEMM #3: out rows = A @ ow^T + ob, scattered to all tokens per bin.
// Block 64 bins x 64 cols, 4 warps (32x32), 3-stage x16KB, 4 CTAs/SM.
// Epilogue: stage (bias-added) 64x64 block in smem, then fully-coalesced
// per-warp row copies (float2 per lane = 256B/warp-instruction) to tokens.
// ---------------------------------------------------------------------------
__global__ __launch_bounds__(128, 4) void out_gemm_kernel(
    const float* __restrict__ ob, float* __restrict__ out)
{
    extern __shared__ char sp[];
    __shared__ float s_ob[64];
    const int t    = threadIdx.x;
    const int lane = t & 31;
    const int w    = t >> 5;
    const int m0w  = (w >> 1) * 32;
    const int n0w  = (w & 1) * 32;
    const int m0   = blockIdx.x * 64;     // rows m = b*512 + g
    const int j0   = blockIdx.y * 64;
    uint32_t sb = smem_u32(sp);

    if (t < 64) s_ob[t] = ob[j0 + t];

    float acc[2][4][4];
    #pragma unroll
    for (int a = 0; a < 2; ++a)
        #pragma unroll
        for (int b = 0; b < 4; ++b)
            #pragma unroll
            for (int q = 0; q < 4; ++q) acc[a][b][q] = 0.f;

    const __half* Abase = g_A  + (size_t)m0 * DD;
    const __half* Bbase = g_ow + (size_t)j0 * DD;

    load_tiles<128,64,64,8192>(Abase,      DD, Bbase,      DD, sb,          t); CP_COMMIT();
    load_tiles<128,64,64,8192>(Abase + KC, DD, Bbase + KC, DD, sb + FSTAGE, t); CP_COMMIT();

    for (int s = 0; s < NCH; ++s) {
        if (s + 2 < NCH) { CP_WAIT1(); } else { CP_WAIT0(); }
        __syncthreads();
        if (s + 2 < NCH) {
            load_tiles<128,64,64,8192>(Abase + (s + 2) * KC, DD, Bbase + (s + 2) * KC, DD,
                                       sb + ((s + 2) % 3) * FSTAGE, t);
            CP_COMMIT();
        }
        compute32x32(sb + (s % 3) * FSTAGE, m0w, n0w, lane, acc);
    }
    __syncthreads();          // mainloop smem reads done; reuse sp for staging

    // stage bias-added block: sC[64][64], pitch 66 floats (16.9KB < 48KB dyn)
    float* sC = reinterpret_cast<float*>(sp);
    #pragma unroll
    for (int mt = 0; mt < 2; ++mt)
        #pragma unroll
        for (int half = 0; half < 2; ++half) {
            int r = m0w + mt * 16 + half * 8 + (lane >> 2);
            #pragma unroll
            for (int nt = 0; nt < 4; ++nt) {
                int cl = n0w + nt * 8 + ((lane & 3) << 1);
                sC[r * 66 + cl]     = acc[mt][nt][half * 2 + 0] + s_ob[cl];
                sC[r * 66 + cl + 1] = acc[mt][nt][half * 2 + 1] + s_ob[cl + 1];
            }
        }
    __syncthreads();

    // coalesced scatter: warp w handles bins w, w+4, ... ; 32 lanes copy one
    // 64-float row as float2 each (256B contiguous per instruction).
    const int b = m0 >> 9;
    for (int mloc = w; mloc < 64; mloc += 4) {
        int g = (m0 + mloc) & 511;
        float2 val = *reinterpret_cast<const float2*>(sC + mloc * 66 + 2 * lane);
        int n = (int)(((long long)g * 4095) / 511) - 2;
        if (n < 0) n = 0;
        while (bin_of(n) < g) ++n;
        for (; n < NN && bin_of(n) == g; ++n) {
            float* dst = out + (((size_t)(b * NN + n)) << 10) + j0;
            *reinterpret_cast<float2*>(dst + 2 * lane) = val;
        }
    }
}

// ---------------------------------------------------------------------------
extern "C" void kernel_launch(void* const* d_in, const int* in_sizes, int n_in,
                              void* d_out, int out_size)
{
    const float* x  = (const float*)d_in[0];
    // d_in[1], d_in[2] are q_w, q_b — unused by the reference output.
    const float* kw = (const float*)d_in[3];
    const float* kb = (const float*)d_in[4];
    const float* vw = (const float*)d_in[5];
    const float* vb = (const float*)d_in[6];
    const float* ow = (const float*)d_in[7];
    const float* ob = (const float*)d_in[8];
    float* out = (float*)d_out;

    cudaFuncSetAttribute(k_gemm_kernel,   cudaFuncAttributeMaxDynamicSharedMemorySize, 2 * KSTAGE);
    cudaFuncSetAttribute(f_gemm_kernel,   cudaFuncAttributeMaxDynamicSharedMemorySize, 3 * FSTAGE);
    cudaFuncSetAttribute(out_gemm_kernel, cudaFuncAttributeMaxDynamicSharedMemorySize, 3 * FSTAGE);
    cudaFuncSetAttribute(conv_kernel, cudaFuncAttributeMaxDynamicSharedMemorySize,
                         GG * HDIM * (int)sizeof(float));

    prep_kernel<<<19456, 256>>>(x, kw, vw, ow);

    k_gemm_kernel<<<dim3(BNTOK / 64, 8), 128, 2 * KSTAGE>>>(kb);

    ysum_kernel<<<BB * GG, 512>>>();

    f_gemm_kernel<<<dim3((BB * GG) / 64, HH), 128, 3 * FSTAGE>>>(vb);

    conv_kernel<<<BB * HH, 512, GG * HDIM * sizeof(float)>>>();

    out_gemm_kernel<<<dim3((BB * GG) / 64, DD / 64), 128, 3 * FSTAGE>>>(ob, out);
}